// round 17
// baseline (speedup 1.0000x reference)
#include <cuda_runtime.h>

// Grid constants (match reference)
#define N_PIX_HI 512
#define NV_HI    256
#define N_PIX_LO 128
#define NV_LO    64
#define OUT_ELEMS (NV_LO * N_PIX_LO * N_PIX_LO)   // 1,048,576

#define INV_PIX_HI_F  40.0f     // 1/0.025 exactly
#define INV_DV_HI_F   0.32f     // 1/3.125 (~1ulp)
#define FOV_HALF_HI_F 6.3875f
#define VEL0_HI_F     -404.6875f

#define NBLK 1184               // 148 SMs x 8 CTAs (persistent-ish)
#define NTHR 256

// Splat one point: R8 16B-quad v4 scheme (lowest op count, straddle P=1/16),
// one asm block, immediate byte offsets (+y row=512B, +v plane=65536B).
__device__ __forceinline__ void splat_point(float rr, float dd, float vv, float ff,
                                            float* __restrict__ out) {
    float x = (rr + FOV_HALF_HI_F) * INV_PIX_HI_F;
    float y = (dd + FOV_HALF_HI_F) * INV_PIX_HI_F;
    float v = (vv - VEL0_HI_F)     * INV_DV_HI_F;

    float xf = floorf(x), yf = floorf(y), vf = floorf(v);
    int ix0 = (int)xf, iy0 = (int)yf, iv0 = (int)vf;
    float fx = x - xf, fy = y - yf, fv = v - vf;

    int valid = ((unsigned)ix0 < N_PIX_HI - 1) &
                ((unsigned)iy0 < N_PIX_HI - 1) &
                ((unsigned)iv0 < NV_HI - 1);

    int sx = (ix0 & 3) == 3;
    int sy = (iy0 & 3) == 3;
    int sv = (iv0 & 3) == 3;

    float wy0 = sy ? (1.0f - fy) : 1.0f;
    float wv0 = sv ? (1.0f - fv) : 1.0f;

    float f = ff * (1.0f / 64.0f);

    int cx0 = ix0 >> 2, cy0 = iy0 >> 2, cv0 = iv0 >> 2;

    // x placement in the aligned 4-cell quad; untouched slots add 0.0f.
    int q = cx0 & 3;
    float t0 = sx ? (1.0f - fx) : 1.0f;
    float t1 = sx ? fx : 0.0f;
    float u0 = (q == 0) ? t0 : 0.0f;
    float u1 = (q == 1) ? t0 : ((q == 0) ? t1 : 0.0f);
    float u2 = (q == 2) ? t0 : ((q == 1) ? t1 : 0.0f);
    float u3 = (q == 3) ? t0 : ((q == 2) ? t1 : 0.0f);
    int st = (q == 3) & sx;               // spill into next quad (P=1/16)

    float* oq = out + ((cv0 * N_PIX_LO + cy0) * N_PIX_LO + (cx0 & ~3));

    float a0 = f * wv0 * wy0;
    float a1 = f * wv0 * fy;
    float a2 = f * fv  * wy0;
    float a3 = f * fv  * fy;

    asm volatile(
        "{\n\t"
        ".reg .pred pv, py, pz, pzy, ps, psy, psz, pszy;\n\t"
        "setp.ne.s32      pv,   %21, 0;\n\t"
        "setp.ne.and.s32  py,   %22, 0, pv;\n\t"
        "setp.ne.and.s32  pz,   %23, 0, pv;\n\t"
        "setp.ne.and.s32  pzy,  %22, 0, pz;\n\t"
        "setp.ne.and.s32  ps,   %24, 0, pv;\n\t"
        "setp.ne.and.s32  psy,  %22, 0, ps;\n\t"
        "setp.ne.and.s32  psz,  %23, 0, ps;\n\t"
        "setp.ne.and.s32  pszy, %22, 0, psz;\n\t"
        "@pv   red.global.add.v4.f32 [%0],       {%1, %2, %3, %4};\n\t"
        "@py   red.global.add.v4.f32 [%0+512],   {%5, %6, %7, %8};\n\t"
        "@pz   red.global.add.v4.f32 [%0+65536], {%9, %10, %11, %12};\n\t"
        "@pzy  red.global.add.v4.f32 [%0+66048], {%13, %14, %15, %16};\n\t"
        "@ps   red.global.add.f32    [%0+16],    %17;\n\t"
        "@psy  red.global.add.f32    [%0+528],   %18;\n\t"
        "@psz  red.global.add.f32    [%0+65552], %19;\n\t"
        "@pszy red.global.add.f32    [%0+66064], %20;\n\t"
        "}"
        :: "l"(oq),
           "f"(a0*u0), "f"(a0*u1), "f"(a0*u2), "f"(a0*u3),
           "f"(a1*u0), "f"(a1*u1), "f"(a1*u2), "f"(a1*u3),
           "f"(a2*u0), "f"(a2*u1), "f"(a2*u2), "f"(a2*u3),
           "f"(a3*u0), "f"(a3*u1), "f"(a3*u2), "f"(a3*u3),
           "f"(a0*t1), "f"(a1*t1), "f"(a2*t1), "f"(a3*t1),
           "r"(valid), "r"(sy), "r"(sv), "r"(st)
        : "memory");
}

__global__ void __launch_bounds__(NTHR) splat_kernel(
        const float* __restrict__ ra,
        const float* __restrict__ dec,
        const float* __restrict__ vel,
        const float* __restrict__ flux,
        float* __restrict__ out,
        int n) {
    const int stride = NBLK * NTHR;
    int i = blockIdx.x * NTHR + threadIdx.x;
    if (i >= n) return;

    // Software pipeline: inputs of iteration j+1 are loaded BEFORE the asm
    // RED block of iteration j (the asm memory clobber would otherwise force
    // load-after-RED ordering and serialize DRAM latency with atomic issue).
    float cr = ra[i], cd = dec[i], cv = vel[i], cf = flux[i];

    for (;;) {
        int nx = i + stride;
        bool more = nx < n;
        int safe = more ? nx : i;
        float nr = ra[safe], nd = dec[safe], nv = vel[safe], nf = flux[safe];

        splat_point(cr, cd, cv, cf, out);

        if (!more) break;
        i = nx;
        cr = nr; cd = nd; cv = nv; cf = nf;
    }
}

extern "C" void kernel_launch(void* const* d_in, const int* in_sizes, int n_in,
                              void* d_out, int out_size) {
    const float* ra   = (const float*)d_in[0];
    const float* dec  = (const float*)d_in[1];
    const float* vel  = (const float*)d_in[2];
    const float* flux = (const float*)d_in[3];
    float* out = (float*)d_out;
    int n = in_sizes[0];

    cudaMemsetAsync(out, 0, OUT_ELEMS * sizeof(float));

    splat_kernel<<<NBLK, NTHR>>>(ra, dec, vel, flux, out, n);
}